// round 4
// baseline (speedup 1.0000x reference)
#include <cuda_runtime.h>
#include <cuda_bf16.h>

// HMM forward (log-space output) via linear-domain recurrence with
// exponent-bit rescaling. See analysis above.
//
//   inputs: Y int32 [N,T], mask f32 [N,T], log_pi f32 [4,1],
//           log_A f32 [4,4], log_B f32 [4,NV]
//   output: alphas f32 [N,4,T]

#define TT    512            // T (hardcoded; N derived from in_sizes)
#define TC    32             // timesteps per chunk
#define NCH   (TT / TC)
#define BLK   128            // threads per block = sequences per block (max)
#define GRID  148            // one block per SM, single wave
#define MAXV  8192           // vocab capacity for static table

// exp(log_B) transposed: one float4 per vocab id = all 4 states' linear emissions.
__device__ float4 g_Bt[MAXV];

__global__ void hmm_prep_kernel(const float* __restrict__ logB, int NV) {
    int i = blockIdx.x * blockDim.x + threadIdx.x;
    if (i < NV) {
        float4 v;
        v.x = expf(logB[0 * NV + i]);
        v.y = expf(logB[1 * NV + i]);
        v.z = expf(logB[2 * NV + i]);
        v.w = expf(logB[3 * NV + i]);
        g_Bt[i] = v;
    }
}

// smem layout (dynamic):
//   float4 buf[BLK][33]   : alpha output staging (padded, conflict-free)
//   int    yb [BLK][33]   : Y chunk
//   float  mb [BLK][33]   : mask chunk
#define SMEM_BYTES (BLK * 33 * (int)sizeof(float4) + BLK * 33 * 4 + BLK * 33 * 4)

__global__ __launch_bounds__(BLK, 1) void hmm_kernel(
    const int*   __restrict__ Y,
    const float* __restrict__ mask,
    const float* __restrict__ logpi,
    const float* __restrict__ logA,
    const float* __restrict__ logB,
    float*       __restrict__ out,
    int N, int NV)
{
    extern __shared__ char smem[];
    float4* buf = (float4*)smem;
    int*    yb  = (int*)(smem + BLK * 33 * sizeof(float4));
    float*  mb  = (float*)(yb + BLK * 33);

    const int tid  = threadIdx.x;
    const int lane = tid & 31;
    const int warp = tid >> 5;

    // Balanced contiguous sequence ranges across GRID blocks.
    const long long bb = blockIdx.x;
    const int base = (int)((bb * (long long)N) / GRID);
    const int end  = (int)(((bb + 1) * (long long)N) / GRID);
    const int cnt  = end - base;
    const bool active = (tid < cnt);

    const float LN2 = 0.69314718055994530942f;
    const float L2E = 1.44269504088896340736f;

    // Linear-domain transition matrix in registers. exp(-1000) == 0.0f exactly,
    // so structural zeros are handled by the dense matvec with no assumptions.
    float A[16];
#pragma unroll
    for (int i = 0; i < 16; i++) A[i] = expf(__ldg(&logA[i]));

    // Recurrence state: scaled linear probs p[4], log-offset c (natural log),
    // previous natural-log alphas ap[4] (for the mask blend path).
    float p0 = 0.f, p1 = 0.f, p2 = 0.f, p3 = 0.f, c = 0.f;
    float ap0 = 0.f, ap1 = 0.f, ap2 = 0.f, ap3 = 0.f;

    for (int ch = 0; ch < NCH; ch++) {
        const int t0 = ch * TC;

        // --- stage Y/mask chunk (warp-local rows, coalesced 128B lines) ---
#pragma unroll 1
        for (int q = 0; q < 32; q++) {
            int row = (warp << 5) + q;
            if (row < cnt) {
                int g = (base + row) * TT + t0 + lane;
                yb[row * 33 + lane] = Y[g];
                mb[row * 33 + lane] = mask[g];
            }
        }
        __syncwarp();

        int jstart = 0;
        if (ch == 0) {
            // t = 0: alpha0 = log_pi + log_B[:, y0]  (exact, from inputs)
            int y0 = active ? yb[tid * 33 + 0] : 0;
            float a0 = __ldg(&logpi[0]) + __ldg(&logB[0 * NV + y0]);
            float a1 = __ldg(&logpi[1]) + __ldg(&logB[1 * NV + y0]);
            float a2 = __ldg(&logpi[2]) + __ldg(&logB[2 * NV + y0]);
            float a3 = __ldg(&logpi[3]) + __ldg(&logB[3 * NV + y0]);
            buf[tid * 33 + 0] = make_float4(a0, a1, a2, a3);
            c = fmaxf(fmaxf(a0, a1), fmaxf(a2, a3));
            p0 = exp2f((a0 - c) * L2E);
            p1 = exp2f((a1 - c) * L2E);
            p2 = exp2f((a2 - c) * L2E);
            p3 = exp2f((a3 - c) * L2E);
            ap0 = a0; ap1 = a1; ap2 = a2; ap3 = a3;
            jstart = 1;
        }

        // prime emission prefetch
        int yy = active ? yb[tid * 33 + jstart] : 0;
        float4 ecur = __ldg(&g_Bt[yy]);

#pragma unroll 4
        for (int j = jstart; j < TC; j++) {
            // prefetch next step's emission (off critical path; L1-resident table)
            int jn = (j + 1 < TC) ? (j + 1) : (TC - 1);
            int yn = active ? yb[tid * 33 + jn] : 0;
            float4 en = __ldg(&g_Bt[yn]);
            float4 e = ecur;

            // q[s] = (sum_p p[p] * A[p][s]) * e[s]   (dense 4x4 matvec)
            float q0 = p0 * A[0];
            q0 = fmaf(p1, A[4],  q0); q0 = fmaf(p2, A[8],  q0); q0 = fmaf(p3, A[12], q0); q0 *= e.x;
            float q1 = p0 * A[1];
            q1 = fmaf(p1, A[5],  q1); q1 = fmaf(p2, A[9],  q1); q1 = fmaf(p3, A[13], q1); q1 *= e.y;
            float q2 = p0 * A[2];
            q2 = fmaf(p1, A[6],  q2); q2 = fmaf(p2, A[10], q2); q2 = fmaf(p3, A[14], q2); q2 *= e.z;
            float q3 = p0 * A[3];
            q3 = fmaf(p1, A[7],  q3); q3 = fmaf(p2, A[11], q3); q3 = fmaf(p3, A[15], q3); q3 *= e.w;

            // power-of-2 rescale from exponent bits (no MUFU, exact offset)
            float mx = fmaxf(fmaxf(q0, q1), fmaxf(q2, q3));
            int   eb = __float_as_int(mx) >> 23;             // biased exponent (mx > 0)
            float scale = __int_as_float((254 - eb) << 23);  // 2^{-E}
            float Ef = (float)(eb - 127);

            // outputs: alpha[s] = log2(q[s]) * ln2 + c
            float an0 = fmaf(__log2f(q0), LN2, c);
            float an1 = fmaf(__log2f(q1), LN2, c);
            float an2 = fmaf(__log2f(q2), LN2, c);
            float an3 = fmaf(__log2f(q3), LN2, c);

            float m = active ? mb[tid * 33 + j] : 1.0f;
            if (m == 1.0f) {
                // fast path: commit rescaled state
                c  = fmaf(Ef, LN2, c);
                p0 = q0 * scale; p1 = q1 * scale; p2 = q2 * scale; p3 = q3 * scale;
            } else {
                // general mask blend: alpha = m*a_t + (1-m)*alpha_prev,
                // then rebuild (p, c) to match the blended alphas.
                an0 = fmaf(m, an0 - ap0, ap0);
                an1 = fmaf(m, an1 - ap1, ap1);
                an2 = fmaf(m, an2 - ap2, ap2);
                an3 = fmaf(m, an3 - ap3, ap3);
                float cm = fmaxf(fmaxf(an0, an1), fmaxf(an2, an3));
                c  = cm;
                p0 = exp2f((an0 - cm) * L2E);
                p1 = exp2f((an1 - cm) * L2E);
                p2 = exp2f((an2 - cm) * L2E);
                p3 = exp2f((an3 - cm) * L2E);
            }
            ap0 = an0; ap1 = an1; ap2 = an2; ap3 = an3;

            buf[tid * 33 + j] = make_float4(an0, an1, an2, an3);
            ecur = en;
        }
        __syncwarp();

        // --- coalesced writeout: per (seq,state) a contiguous 128B line ---
#pragma unroll 1
        for (int q = 0; q < 32; q++) {
            int row = (warp << 5) + q;
            if (row < cnt) {
                float4 v = buf[row * 33 + lane];   // lane = time within chunk
                int o = (base + row) * (4 * TT) + t0 + lane;
                out[o]          = v.x;
                out[o + TT]     = v.y;
                out[o + 2 * TT] = v.z;
                out[o + 3 * TT] = v.w;
            }
        }
        __syncwarp();
    }
}

extern "C" void kernel_launch(void* const* d_in, const int* in_sizes, int n_in,
                              void* d_out, int out_size) {
    const int*   Y     = (const int*)  d_in[0];
    const float* mask  = (const float*)d_in[1];
    const float* logpi = (const float*)d_in[2];
    const float* logA  = (const float*)d_in[3];
    const float* logB  = (const float*)d_in[4];
    float*       out   = (float*)d_out;

    const int N  = in_sizes[0] / TT;      // Y is [N, T]
    const int NV = in_sizes[4] / 4;       // log_B is [4, NV]

    cudaFuncSetAttribute(hmm_kernel,
                         cudaFuncAttributeMaxDynamicSharedMemorySize, SMEM_BYTES);

    hmm_prep_kernel<<<(NV + 127) / 128, 128>>>(logB, NV);
    hmm_kernel<<<GRID, BLK, SMEM_BYTES>>>(Y, mask, logpi, logA, logB, out, N, NV);
}

// round 5
// speedup vs baseline: 3.1834x; 3.1834x over previous
#include <cuda_runtime.h>
#include <cuda_bf16.h>

// HMM forward, time-parallel 3-phase decomposition.
//   pass1 : per (seq,chunk k=1..14) 4x4 chunk transfer matrix (fma-bound)
//   mid   : per seq, scalar chunk0 + 14 matvecs -> exact chunk-start log-alphas
//   pass2 : per (seq,chunk) recompute 32 alphas, smem-table gathers,
//           reg-transpose + padded-smem staging -> coalesced stores
// Linear-domain recurrence with exponent-bit rescaling; logs only on output.

#define TT   512
#define NSEQ 16384
#define KM   14
#define MAXV 8192
#define LN2f 0.69314718055994530942f
#define L2Ef 1.44269504088896340736f

__device__ uint2  g_BtH[MAXV];          // bf16x4 linear emissions per token
__device__ float4 g_M [KM * 4 * NSEQ];  // chunk matrices [k-1][row][seq]
__device__ float  g_Mc[KM * NSEQ];      // chunk matrix log offsets
__device__ float4 g_S [16 * NSEQ];      // log-alpha at t=32k-1, k=1..15

struct W8 { float AEB, ASB, ABM, AMM, ABE, AME, AES, ASS; };

// A[p][s] = logA[p*4+s]; allowed preds: in(B)={E,S}, in(M)=in(E)={B,M}, in(S)={E,S}
__device__ __forceinline__ W8 load_w(const float* __restrict__ logA) {
    W8 w;
    w.AEB = expf(__ldg(&logA[8]));
    w.ASB = expf(__ldg(&logA[12]));
    w.ABM = expf(__ldg(&logA[1]));
    w.AMM = expf(__ldg(&logA[5]));
    w.ABE = expf(__ldg(&logA[2]));
    w.AME = expf(__ldg(&logA[6]));
    w.AES = expf(__ldg(&logA[11]));
    w.ASS = expf(__ldg(&logA[15]));
    return w;
}

__device__ __forceinline__ void unp(uint2 v, float& e0, float& e1, float& e2, float& e3) {
    e0 = __uint_as_float(v.x << 16);
    e1 = __uint_as_float(v.x & 0xFFFF0000u);
    e2 = __uint_as_float(v.y << 16);
    e3 = __uint_as_float(v.y & 0xFFFF0000u);
}

__device__ __forceinline__ float getc(float4 a, int s) {
    return s == 0 ? a.x : s == 1 ? a.y : s == 2 ? a.z : a.w;
}

// ---------------- prep: bf16x4 emission table ----------------
__global__ void prep_kernel(const float* __restrict__ logB, int NV) {
    int i = blockIdx.x * blockDim.x + threadIdx.x;
    if (i >= NV) return;
    unsigned b0 = (unsigned)__bfloat16_as_ushort(__float2bfloat16(expf(logB[i])));
    unsigned b1 = (unsigned)__bfloat16_as_ushort(__float2bfloat16(expf(logB[NV + i])));
    unsigned b2 = (unsigned)__bfloat16_as_ushort(__float2bfloat16(expf(logB[2 * NV + i])));
    unsigned b3 = (unsigned)__bfloat16_as_ushort(__float2bfloat16(expf(logB[3 * NV + i])));
    uint2 v; v.x = b0 | (b1 << 16); v.y = b2 | (b3 << 16);
    g_BtH[i] = v;
}

// ---------------- pass1: chunk transfer matrices ----------------
__global__ __launch_bounds__(256, 3) void pass1_kernel(
    const int* __restrict__ Y, const float* __restrict__ mask,
    const float* __restrict__ logA, int N, int NV)
{
    extern __shared__ uint2 s_tab1[];
    for (int i = threadIdx.x; i < NV; i += 256) s_tab1[i] = g_BtH[i];
    __syncthreads();

    int tau = blockIdx.x * 256 + threadIdx.x;
    if (tau >= KM * N) return;
    int k   = tau / N + 1;               // 1..14
    int seq = tau - (k - 1) * N;

    W8 w = load_w(logA);
    float4 M0 = {1, 0, 0, 0}, M1 = {0, 1, 0, 0}, M2 = {0, 0, 1, 0}, M3 = {0, 0, 0, 1};
    float c = 0.f;
    const int4*   yp = (const int4*)(Y    + (size_t)seq * TT + 32 * k);
    const float4* mp = (const float4*)(mask + (size_t)seq * TT + 32 * k);

#pragma unroll 1
    for (int jj = 0; jj < 8; jj++) {
        int4   y4 = __ldg(yp + jj);
        float4 m4 = __ldg(mp + jj);
        int   ya[4] = {y4.x, y4.y, y4.z, y4.w};
        float ma[4] = {m4.x, m4.y, m4.z, m4.w};
#pragma unroll
        for (int q = 0; q < 4; q++) {
            uint2 ev = s_tab1[ya[q]];
            if (ma[q] == 1.0f) {
                float e0, e1, e2, e3; unp(ev, e0, e1, e2, e3);
                float u, v;
                u = e0 * w.AEB; v = e0 * w.ASB;   // row B <- rows E,S
                float4 n0 = {fmaf(v, M3.x, u * M2.x), fmaf(v, M3.y, u * M2.y),
                             fmaf(v, M3.z, u * M2.z), fmaf(v, M3.w, u * M2.w)};
                u = e1 * w.ABM; v = e1 * w.AMM;   // row M <- rows B,M
                float4 n1 = {fmaf(v, M1.x, u * M0.x), fmaf(v, M1.y, u * M0.y),
                             fmaf(v, M1.z, u * M0.z), fmaf(v, M1.w, u * M0.w)};
                u = e2 * w.ABE; v = e2 * w.AME;   // row E <- rows B,M
                float4 n2 = {fmaf(v, M1.x, u * M0.x), fmaf(v, M1.y, u * M0.y),
                             fmaf(v, M1.z, u * M0.z), fmaf(v, M1.w, u * M0.w)};
                u = e3 * w.AES; v = e3 * w.ASS;   // row S <- rows E,S
                float4 n3 = {fmaf(v, M3.x, u * M2.x), fmaf(v, M3.y, u * M2.y),
                             fmaf(v, M3.z, u * M2.z), fmaf(v, M3.w, u * M2.w)};
                M0 = n0; M1 = n1; M2 = n2; M3 = n3;
            }
        }
        // rescale (exponent bits, exact)
        float mx = fmaxf(fmaxf(fmaxf(fmaxf(M0.x, M0.y), fmaxf(M0.z, M0.w)),
                               fmaxf(fmaxf(M1.x, M1.y), fmaxf(M1.z, M1.w))),
                         fmaxf(fmaxf(fmaxf(M2.x, M2.y), fmaxf(M2.z, M2.w)),
                               fmaxf(fmaxf(M3.x, M3.y), fmaxf(M3.z, M3.w))));
        int eb = __float_as_int(mx) >> 23;
        float sc = __int_as_float((254 - eb) << 23);
        c = fmaf((float)(eb - 127), LN2f, c);
        M0.x *= sc; M0.y *= sc; M0.z *= sc; M0.w *= sc;
        M1.x *= sc; M1.y *= sc; M1.z *= sc; M1.w *= sc;
        M2.x *= sc; M2.y *= sc; M2.z *= sc; M2.w *= sc;
        M3.x *= sc; M3.y *= sc; M3.z *= sc; M3.w *= sc;
    }
    int b = ((k - 1) * 4) * N + seq;
    g_M[b] = M0; g_M[b + N] = M1; g_M[b + 2 * N] = M2; g_M[b + 3 * N] = M3;
    g_Mc[(k - 1) * N + seq] = c;
}

// ---------------- middle: chunk-boundary log-alphas ----------------
__global__ __launch_bounds__(256) void mid_kernel(
    const int* __restrict__ Y, const float* __restrict__ mask,
    const float* __restrict__ logpi, const float* __restrict__ logA,
    const float* __restrict__ logB, int N, int NV)
{
    int seq = blockIdx.x * 256 + threadIdx.x;
    if (seq >= N) return;
    W8 w = load_w(logA);

    int y0 = __ldg(&Y[(size_t)seq * TT]);
    float a0 = __ldg(&logpi[0]) + __ldg(&logB[y0]);
    float a1 = __ldg(&logpi[1]) + __ldg(&logB[NV + y0]);
    float a2 = __ldg(&logpi[2]) + __ldg(&logB[2 * NV + y0]);
    float a3 = __ldg(&logpi[3]) + __ldg(&logB[3 * NV + y0]);
    float c = fmaxf(fmaxf(a0, a1), fmaxf(a2, a3));
    float p0 = exp2f((a0 - c) * L2Ef), p1 = exp2f((a1 - c) * L2Ef);
    float p2 = exp2f((a2 - c) * L2Ef), p3 = exp2f((a3 - c) * L2Ef);

    for (int t = 1; t < 32; t++) {
        int   y = __ldg(&Y[(size_t)seq * TT + t]);
        float m = __ldg(&mask[(size_t)seq * TT + t]);
        uint2 ev = __ldg(&g_BtH[y]);
        if (m == 1.0f) {
            float e0, e1, e2, e3; unp(ev, e0, e1, e2, e3);
            float qB = e0 * fmaf(w.ASB, p3, w.AEB * p2);
            float qM = e1 * fmaf(w.AMM, p1, w.ABM * p0);
            float qE = e2 * fmaf(w.AME, p1, w.ABE * p0);
            float qS = e3 * fmaf(w.ASS, p3, w.AES * p2);
            float mx = fmaxf(fmaxf(qB, qM), fmaxf(qE, qS));
            int eb = __float_as_int(mx) >> 23;
            float sc = __int_as_float((254 - eb) << 23);
            c = fmaf((float)(eb - 127), LN2f, c);
            p0 = qB * sc; p1 = qM * sc; p2 = qE * sc; p3 = qS * sc;
        }
    }
    g_S[1 * N + seq] = make_float4(fmaf(__log2f(p0), LN2f, c), fmaf(__log2f(p1), LN2f, c),
                                   fmaf(__log2f(p2), LN2f, c), fmaf(__log2f(p3), LN2f, c));
    for (int k = 1; k <= KM; k++) {
        int b = ((k - 1) * 4) * N + seq;
        float4 r0 = __ldg(&g_M[b]);
        float4 r1 = __ldg(&g_M[b + N]);
        float4 r2 = __ldg(&g_M[b + 2 * N]);
        float4 r3 = __ldg(&g_M[b + 3 * N]);
        float cm = __ldg(&g_Mc[(k - 1) * N + seq]);
        float q0 = fmaf(r0.x, p0, fmaf(r0.y, p1, fmaf(r0.z, p2, r0.w * p3)));
        float q1 = fmaf(r1.x, p0, fmaf(r1.y, p1, fmaf(r1.z, p2, r1.w * p3)));
        float q2 = fmaf(r2.x, p0, fmaf(r2.y, p1, fmaf(r2.z, p2, r2.w * p3)));
        float q3 = fmaf(r3.x, p0, fmaf(r3.y, p1, fmaf(r3.z, p2, r3.w * p3)));
        c += cm;
        float mx = fmaxf(fmaxf(q0, q1), fmaxf(q2, q3));
        int eb = __float_as_int(mx) >> 23;
        float sc = __int_as_float((254 - eb) << 23);
        c = fmaf((float)(eb - 127), LN2f, c);
        p0 = q0 * sc; p1 = q1 * sc; p2 = q2 * sc; p3 = q3 * sc;
        g_S[(k + 1) * N + seq] =
            make_float4(fmaf(__log2f(p0), LN2f, c), fmaf(__log2f(p1), LN2f, c),
                        fmaf(__log2f(p2), LN2f, c), fmaf(__log2f(p3), LN2f, c));
    }
}

// ---------------- pass2: emit all alphas ----------------
// block = 256 threads = 16 seqs x 16 chunks. smem: bf16 table + staging buf
// (stride-12 rows: 8 step-floats + 4 pad -> aligned STS.128, ~conflict-free LDS).
__global__ __launch_bounds__(256, 2) void pass2_kernel(
    const int* __restrict__ Y, const float* __restrict__ mask,
    const float* __restrict__ logpi, const float* __restrict__ logA,
    const float* __restrict__ logB, float* __restrict__ out, int N, int NV)
{
    extern __shared__ char smem[];
    uint2* tab = (uint2*)smem;
    float* buf = (float*)(smem + (size_t)NV * 8);
    for (int i = threadIdx.x; i < NV; i += 256) tab[i] = g_BtH[i];
    __syncthreads();

    const int tid = threadIdx.x, lane = tid & 31, wid = tid >> 5;
    const int seq_l = tid >> 4, k = tid & 15;
    const int bseq = blockIdx.x * 16;
    const int seq = bseq + seq_l;
    W8 w = load_w(logA);

    float p0, p1, p2, p3, c, ap0, ap1, ap2, ap3;
    if (k == 0) {
        int y0 = __ldg(&Y[(size_t)seq * TT]);
        ap0 = __ldg(&logpi[0]) + __ldg(&logB[y0]);
        ap1 = __ldg(&logpi[1]) + __ldg(&logB[NV + y0]);
        ap2 = __ldg(&logpi[2]) + __ldg(&logB[2 * NV + y0]);
        ap3 = __ldg(&logpi[3]) + __ldg(&logB[3 * NV + y0]);
    } else {
        float4 a = __ldg(&g_S[k * N + seq]);
        ap0 = a.x; ap1 = a.y; ap2 = a.z; ap3 = a.w;
    }
    c  = fmaxf(fmaxf(ap0, ap1), fmaxf(ap2, ap3));
    p0 = exp2f((ap0 - c) * L2Ef); p1 = exp2f((ap1 - c) * L2Ef);
    p2 = exp2f((ap2 - c) * L2Ef); p3 = exp2f((ap3 - c) * L2Ef);

    const size_t ybase = (size_t)seq * TT + 32 * k;

#pragma unroll 1
    for (int g = 0; g < 4; g++) {
        float4 an[8];
        int4 y4 = {0, 0, 0, 0}; float4 m4 = {0, 0, 0, 0};
#pragma unroll
        for (int j = 0; j < 8; j++) {
            if ((j & 3) == 0) {
                y4 = __ldg((const int4*)(Y + ybase + g * 8 + j));
                m4 = __ldg((const float4*)(mask + ybase + g * 8 + j));
            }
            int y; float m;
            switch (j & 3) {
                case 0:  y = y4.x; m = m4.x; break;
                case 1:  y = y4.y; m = m4.y; break;
                case 2:  y = y4.z; m = m4.z; break;
                default: y = y4.w; m = m4.w; break;
            }
            uint2 ev = tab[y];
            if (k == 0 && g == 0 && j == 0) {
                an[0] = make_float4(ap0, ap1, ap2, ap3);  // t=0: exact logs
            } else {
                float e0, e1, e2, e3; unp(ev, e0, e1, e2, e3);
                float qB = e0 * fmaf(w.ASB, p3, w.AEB * p2);
                float qM = e1 * fmaf(w.AMM, p1, w.ABM * p0);
                float qE = e2 * fmaf(w.AME, p1, w.ABE * p0);
                float qS = e3 * fmaf(w.ASS, p3, w.AES * p2);
                float n0 = fmaf(__log2f(qB), LN2f, c);
                float n1 = fmaf(__log2f(qM), LN2f, c);
                float n2 = fmaf(__log2f(qE), LN2f, c);
                float n3 = fmaf(__log2f(qS), LN2f, c);
                if (m == 1.0f) {
                    p0 = qB; p1 = qM; p2 = qE; p3 = qS;
                    if ((j & 3) == 3) {
                        float mx = fmaxf(fmaxf(p0, p1), fmaxf(p2, p3));
                        int eb = __float_as_int(mx) >> 23;
                        float sc = __int_as_float((254 - eb) << 23);
                        c = fmaf((float)(eb - 127), LN2f, c);
                        p0 *= sc; p1 *= sc; p2 *= sc; p3 *= sc;
                    }
                } else {
                    // log-domain blend (exact for any m); rebuild (p,c)
                    n0 = fmaf(m, n0 - ap0, ap0);
                    n1 = fmaf(m, n1 - ap1, ap1);
                    n2 = fmaf(m, n2 - ap2, ap2);
                    n3 = fmaf(m, n3 - ap3, ap3);
                    c  = fmaxf(fmaxf(n0, n1), fmaxf(n2, n3));
                    p0 = exp2f((n0 - c) * L2Ef); p1 = exp2f((n1 - c) * L2Ef);
                    p2 = exp2f((n2 - c) * L2Ef); p3 = exp2f((n3 - c) * L2Ef);
                }
                ap0 = n0; ap1 = n1; ap2 = n2; ap3 = n3;
                an[j] = make_float4(n0, n1, n2, n3);
            }
        }
        // reg-transpose -> staging (stride 12 floats/row: aligned float4 stores)
#pragma unroll
        for (int s = 0; s < 4; s++) {
            float4 v0 = make_float4(getc(an[0], s), getc(an[1], s), getc(an[2], s), getc(an[3], s));
            float4 v1 = make_float4(getc(an[4], s), getc(an[5], s), getc(an[6], s), getc(an[7], s));
            *(float4*)&buf[s * 3072 + tid * 12]     = v0;
            *(float4*)&buf[s * 3072 + tid * 12 + 4] = v1;
        }
        __syncthreads();
        // coalesced writeout: 64 (state,seq) rows x 128 floats
        for (int rg = wid; rg < 64; rg += 8) {
            int s = rg >> 4, sl = rg & 15;
            float* dst = out + ((size_t)(bseq + sl) * 4 + s) * TT + g * 8;
            int srcB = s * 3072 + sl * 16 * 12;
#pragma unroll
            for (int it = 0; it < 4; it++) {
                int idx = it * 32 + lane;
                int kk = idx >> 3, j = idx & 7;
                dst[kk * 32 + j] = buf[srcB + kk * 12 + j];
            }
        }
        __syncthreads();
    }
}

extern "C" void kernel_launch(void* const* d_in, const int* in_sizes, int n_in,
                              void* d_out, int out_size) {
    const int*   Y     = (const int*)  d_in[0];
    const float* mask  = (const float*)d_in[1];
    const float* logpi = (const float*)d_in[2];
    const float* logA  = (const float*)d_in[3];
    const float* logB  = (const float*)d_in[4];
    float*       out   = (float*)d_out;

    const int N  = in_sizes[0] / TT;
    const int NV = in_sizes[4] / 4;

    const int smem1 = NV * 8;                    // 48000 B
    const int smem2 = NV * 8 + 4 * 3072 * 4;     // 97152 B

    cudaFuncSetAttribute(pass1_kernel, cudaFuncAttributeMaxDynamicSharedMemorySize, smem1);
    cudaFuncSetAttribute(pass2_kernel, cudaFuncAttributeMaxDynamicSharedMemorySize, smem2);

    prep_kernel<<<(NV + 255) / 256, 256>>>(logB, NV);
    pass1_kernel<<<(KM * N + 255) / 256, 256, smem1>>>(Y, mask, logA, N, NV);
    mid_kernel<<<(N + 255) / 256, 256>>>(Y, mask, logpi, logA, logB, N, NV);
    pass2_kernel<<<N / 16, 256, smem2>>>(Y, mask, logpi, logA, logB, out, N, NV);
}